// round 8
// baseline (speedup 1.0000x reference)
#include <cuda_runtime.h>
#include <cstdint>

// TropicalLinear forward on GB300:
//   out[n,o] = max_i( x[n,i] + w[o,i] ) + bias[o]
//
// R7: fused kernel, occupancy-driven redesign.
//   - natural row-major smem tiles (stride 68 floats = 272B, conflict-free
//     per-phase for LDS.128), NO transpose, NO duplication -> 51 KB smem
//   - k-pair packed add.rn.f32x2 (adjacent k's are already packed in memory)
//   - 256 CTAs (8 o x 2 n x 16 k-splits), 512 thr, __launch_bounds__(512,2)
//     -> 2 CTAs/SM guaranteed (regs<=64, smem 2x51KB, 256 <= 304 slots)
//   - ticket spin barrier (monotonic, replay-safe), fused combine.

#define N_ROWS  128
#define IN_DIM  1024
#define OUT_DIM 1024
#define SPLIT   16
#define KC      (IN_DIM / SPLIT)   // 64 k per CTA, single smem stage
#define TN      64
#define TO      128
#define NCTA    256
#define LDS_STRIDE 68              // floats; 272 B, 16B-aligned, bank-clean

// 16 * 128 * 1024 floats = 8 MB static scratch (allocation-free rule)
__device__ float        g_part[SPLIT * N_ROWS * OUT_DIM];
__device__ unsigned int g_arrive;   // zero-init; monotonic across replays

__device__ __forceinline__ float neg_inf() { return __int_as_float(0xff800000); }

__device__ __forceinline__ unsigned long long add2(unsigned long long a,
                                                   unsigned long long b) {
    unsigned long long r;
    asm("add.rn.f32x2 %0, %1, %2;" : "=l"(r) : "l"(a), "l"(b));
    return r;
}
__device__ __forceinline__ float lo32(unsigned long long v) {
    return __uint_as_float((unsigned int)v);
}
__device__ __forceinline__ float hi32(unsigned long long v) {
    return __uint_as_float((unsigned int)(v >> 32));
}

extern "C" __global__ void __launch_bounds__(512, 2)
tropical_fused_kernel(const float* __restrict__ x,
                      const float* __restrict__ w,
                      const float* __restrict__ bias,
                      float* __restrict__ out)
{
    // xs: TN(64) rows x 68  = 17.0 KB ; ws: TO(128) rows x 68 = 34.0 KB
    extern __shared__ float smem[];
    float* xs = smem;                        // [64][68]
    float* ws = smem + TN * LDS_STRIDE;      // [128][68]

    const int tid = threadIdx.x;
    const int tx  = tid & 31;                // o-direction (32 x 4 = 128)
    const int ty  = tid >> 5;                // n-direction (16 x 4 = 64)

    const int o0 = blockIdx.x * TO;
    const int n0 = blockIdx.y * TN;
    const int k0 = blockIdx.z * KC;
    const int flat_cta = blockIdx.x + blockIdx.y * 8 + blockIdx.z * 16; // 0..255

    // ---- stage tiles (natural layout, coalesced LDG.128, bank-clean STS) ----
    // w tile: 128 rows x 16 float4 = 2048 float4; 4 per thread
#pragma unroll
    for (int i = 0; i < 4; ++i) {
        const int idx = tid + i * 512;
        const int row = idx >> 4;
        const int c4  = idx & 15;
        float4 v = *(const float4*)(w + (size_t)(o0 + row) * IN_DIM + k0 + c4 * 4);
        *(float4*)&ws[row * LDS_STRIDE + c4 * 4] = v;
    }
    // x tile: 64 rows x 16 float4 = 1024 float4; 2 per thread
#pragma unroll
    for (int i = 0; i < 2; ++i) {
        const int idx = tid + i * 512;
        const int row = idx >> 4;
        const int c4  = idx & 15;
        float4 v = *(const float4*)(x + (size_t)(n0 + row) * IN_DIM + k0 + c4 * 4);
        *(float4*)&xs[row * LDS_STRIDE + c4 * 4] = v;
    }
    __syncthreads();

    float acc[4][4];
#pragma unroll
    for (int i = 0; i < 4; ++i)
#pragma unroll
        for (int j = 0; j < 4; ++j)
            acc[i][j] = neg_inf();

    // ---- compute: per 4-k block = 8 LDS.128 + 32 ADD.F32X2 + 64 FMNMX ----
    // xs read: all lanes of a warp share ty -> broadcast.
    // ws read: lane tx -> banks (4*tx + 17j + k) mod 32, conflict-free per phase.
#pragma unroll 1
    for (int kb = 0; kb < KC; kb += 4) {
        ulonglong2 xv[4], wv[4];
#pragma unroll
        for (int i = 0; i < 4; ++i)
            xv[i] = *(const ulonglong2*)&xs[(ty * 4 + i) * LDS_STRIDE + kb];
#pragma unroll
        for (int j = 0; j < 4; ++j)
            wv[j] = *(const ulonglong2*)&ws[(tx * 4 + j) * LDS_STRIDE + kb];
#pragma unroll
        for (int i = 0; i < 4; ++i) {
#pragma unroll
            for (int j = 0; j < 4; ++j) {
                unsigned long long s0 = add2(xv[i].x, wv[j].x);  // k, k+1
                unsigned long long s1 = add2(xv[i].y, wv[j].y);  // k+2, k+3
                float m0 = fmaxf(lo32(s0), hi32(s0));
                float m1 = fmaxf(lo32(s1), hi32(s1));
                acc[i][j] = fmaxf(acc[i][j], fmaxf(m0, m1));
            }
        }
    }

    // ---- write partial maxes (coalesced) ----
    float* pbase = g_part + (size_t)blockIdx.z * (N_ROWS * OUT_DIM);
#pragma unroll
    for (int i = 0; i < 4; ++i) {
        const int row = n0 + ty * 4 + i;
        float4 a = make_float4(acc[i][0], acc[i][1], acc[i][2], acc[i][3]);
        *(float4*)(pbase + (size_t)row * OUT_DIM + o0 + tx * 4) = a;
    }

    // ---- grid-wide barrier: monotonic ticket epochs (replay-safe) ----
    __threadfence();
    __syncthreads();
    if (tid == 0) {
        unsigned int ticket = atomicAdd(&g_arrive, 1u) + 1u;
        unsigned int target = ((ticket + NCTA - 1u) / NCTA) * NCTA;
        unsigned int v;
        do {
            asm volatile("ld.acquire.gpu.u32 %0, [%1];"
                         : "=r"(v) : "l"(&g_arrive) : "memory");
        } while (v < target);
    }
    __syncthreads();

    // ---- fused combine: CTAs 0..127 each reduce one output row ----
    if (flat_cta < N_ROWS && tid < 256) {
        const int n  = flat_cta;
        const int o4 = tid * 4;
        const float* p = g_part + (size_t)n * OUT_DIM + o4;
        float4 m = make_float4(neg_inf(), neg_inf(), neg_inf(), neg_inf());
#pragma unroll
        for (int s = 0; s < SPLIT; ++s) {
            float4 v = __ldcg((const float4*)(p + (size_t)s * (N_ROWS * OUT_DIM)));
            m.x = fmaxf(m.x, v.x);
            m.y = fmaxf(m.y, v.y);
            m.z = fmaxf(m.z, v.z);
            m.w = fmaxf(m.w, v.w);
        }
        float4 b = *(const float4*)(bias + o4);
        m.x += b.x; m.y += b.y; m.z += b.z; m.w += b.w;
        *(float4*)(out + (size_t)n * OUT_DIM + o4) = m;
    }
}

extern "C" void kernel_launch(void* const* d_in, const int* in_sizes, int n_in,
                              void* d_out, int out_size)
{
    const float* x    = (const float*)d_in[0];   // [128, 1024]
    const float* w    = (const float*)d_in[1];   // [1024, 1024]
    const float* bias = (const float*)d_in[2];   // [1024]
    float* out = (float*)d_out;                  // [128, 1024]

    const int smem_bytes = (TN + TO) * LDS_STRIDE * sizeof(float);  // 52224 B
    static bool attr_set = false;
    if (!attr_set) {
        cudaFuncSetAttribute(tropical_fused_kernel,
                             cudaFuncAttributeMaxDynamicSharedMemorySize, smem_bytes);
        attr_set = true;
    }

    dim3 grid(OUT_DIM / TO, N_ROWS / TN, SPLIT);  // (8, 2, 16) = 256 CTAs
    tropical_fused_kernel<<<grid, 512, smem_bytes>>>(x, w, bias, out);
}

// round 9
// speedup vs baseline: 1.3034x; 1.3034x over previous
#include <cuda_runtime.h>
#include <cstdint>

// TropicalLinear forward on GB300:
//   out[n,o] = max_i( x[n,i] + w[o,i] ) + bias[o]
//
// R8 = R4 compute core (k-major transposed smem, conflict-free LDS,
//      o-pair packed add.rn.f32x2 with x duplicated) x R7 occupancy recipe
//      (__launch_bounds__(512,2) -> <=64 regs -> 2 CTAs/SM, 256 CTAs).
//   - SPLIT=16, KC=KS=64: single smem stage, one __syncthreads before compute
//   - ticket spin barrier (monotonic, replay-safe), fused combine (16 partials)

#define N_ROWS  128
#define IN_DIM  1024
#define OUT_DIM 1024
#define SPLIT   16
#define KC      (IN_DIM / SPLIT)   // 64 k per CTA
#define KS      64                 // == KC, single stage
#define TN      64
#define TO      128
#define NCTA    256

// 16 * 128 * 1024 floats = 8 MB static scratch (allocation-free rule)
__device__ float        g_part[SPLIT * N_ROWS * OUT_DIM];
__device__ unsigned int g_arrive;   // zero-init; monotonic across replays

__device__ __forceinline__ float neg_inf() { return __int_as_float(0xff800000); }

__device__ __forceinline__ unsigned long long add2(unsigned long long a,
                                                   unsigned long long b) {
    unsigned long long r;
    asm("add.rn.f32x2 %0, %1, %2;" : "=l"(r) : "l"(a), "l"(b));
    return r;
}
__device__ __forceinline__ float lo32(unsigned long long v) {
    return __uint_as_float((unsigned int)v);
}
__device__ __forceinline__ float hi32(unsigned long long v) {
    return __uint_as_float((unsigned int)(v >> 32));
}

extern "C" __global__ void __launch_bounds__(512, 2)
tropical_fused_kernel(const float* __restrict__ x,
                      const float* __restrict__ w,
                      const float* __restrict__ bias,
                      float* __restrict__ out)
{
    // xs2: [KS][2*TN] = 64 x 128 floats (32 KB, x duplicated (v,v) pairs)
    // ws : [KS][TO]   = 64 x 128 floats (32 KB)
    extern __shared__ float smem[];
    float* xs2 = smem;                   // k-major, duplicated x
    float* ws  = smem + KS * 2 * TN;     // k-major w

    const int tid  = threadIdx.x;
    const int tx   = tid & 31;           // o-direction (32 x 4 = 128)
    const int ty   = tid >> 5;           // n-direction (16 x 4 = 64); == warp
    const int warp = ty;
    const int lane = tx;

    const int o0 = blockIdx.x * TO;
    const int n0 = blockIdx.y * TN;
    const int k0 = blockIdx.z * KC;
    const int flat_cta = blockIdx.x + blockIdx.y * 8 + blockIdx.z * 16; // 0..255

    // ---- stage tiles, transposed to k-major; x duplicated (v,v) ----
    // warp owns k-group warp*4 (4 k's); lanes span rows.
    // xs2 STS: float2, lane stride 2 floats -> 16-lane phases hit banks
    //   {0,2,..,30} twice-disjoint -> conflict-free.
    // ws STS: scalar, lane stride 1 -> conflict-free.
    {
        const int kk = warp * 4;
        // x tile: 64 rows, duplicated pairs
#pragma unroll
        for (int rr = 0; rr < 2; ++rr) {
            const int row = lane + rr * 32;
            float4 v = *(const float4*)(x + (size_t)(n0 + row) * IN_DIM + k0 + kk);
            *(float2*)&xs2[(kk + 0) * (2 * TN) + 2 * row] = make_float2(v.x, v.x);
            *(float2*)&xs2[(kk + 1) * (2 * TN) + 2 * row] = make_float2(v.y, v.y);
            *(float2*)&xs2[(kk + 2) * (2 * TN) + 2 * row] = make_float2(v.z, v.z);
            *(float2*)&xs2[(kk + 3) * (2 * TN) + 2 * row] = make_float2(v.w, v.w);
        }
        // w tile: 128 rows
#pragma unroll
        for (int rr = 0; rr < 4; ++rr) {
            const int row = lane + rr * 32;
            float4 v = *(const float4*)(w + (size_t)(o0 + row) * IN_DIM + k0 + kk);
            ws[(kk + 0) * TO + row] = v.x;
            ws[(kk + 1) * TO + row] = v.y;
            ws[(kk + 2) * TO + row] = v.z;
            ws[(kk + 3) * TO + row] = v.w;
        }
    }
    __syncthreads();

    float acc[4][4];
#pragma unroll
    for (int i = 0; i < 4; ++i)
#pragma unroll
        for (int j = 0; j < 4; ++j)
            acc[i][j] = neg_inf();

    // ---- compute: per k = 3 LDS.128 + 8 ADD.F32X2 + 16 FMNMX (16 pairs) ----
    // xs2 reads: all lanes share ty -> warp broadcast (no conflict).
    // ws read: lanes contiguous float4 -> each 8-lane phase covers 32 banks.
#pragma unroll 4
    for (int k = 0; k < KS; ++k) {
        const ulonglong2 xa = *(const ulonglong2*)&xs2[k * (2 * TN) + ty * 8];
        const ulonglong2 xb = *(const ulonglong2*)&xs2[k * (2 * TN) + ty * 8 + 4];
        const ulonglong2 wv = *(const ulonglong2*)&ws[k * TO + tx * 4];
        unsigned long long xd[4] = {xa.x, xa.y, xb.x, xb.y};
        unsigned long long wp[2] = {wv.x, wv.y};
#pragma unroll
        for (int i = 0; i < 4; ++i) {
#pragma unroll
            for (int jp = 0; jp < 2; ++jp) {
                unsigned long long s = add2(xd[i], wp[jp]);
                acc[i][jp * 2 + 0] = fmaxf(acc[i][jp * 2 + 0], lo32(s));
                acc[i][jp * 2 + 1] = fmaxf(acc[i][jp * 2 + 1], hi32(s));
            }
        }
    }

    // ---- write partial maxes (coalesced) ----
    float* pbase = g_part + (size_t)blockIdx.z * (N_ROWS * OUT_DIM);
#pragma unroll
    for (int i = 0; i < 4; ++i) {
        const int row = n0 + ty * 4 + i;
        float4 a = make_float4(acc[i][0], acc[i][1], acc[i][2], acc[i][3]);
        *(float4*)(pbase + (size_t)row * OUT_DIM + o0 + tx * 4) = a;
    }

    // ---- grid-wide barrier: monotonic ticket epochs (replay-safe) ----
    __threadfence();
    __syncthreads();
    if (tid == 0) {
        unsigned int ticket = atomicAdd(&g_arrive, 1u) + 1u;
        unsigned int target = ((ticket + NCTA - 1u) / NCTA) * NCTA;
        unsigned int v;
        do {
            asm volatile("ld.acquire.gpu.u32 %0, [%1];"
                         : "=r"(v) : "l"(&g_arrive) : "memory");
        } while (v < target);
    }
    __syncthreads();

    // ---- fused combine: CTAs 0..127 each reduce one output row ----
    if (flat_cta < N_ROWS && tid < 256) {
        const int n  = flat_cta;
        const int o4 = tid * 4;
        const float* p = g_part + (size_t)n * OUT_DIM + o4;
        float4 m = make_float4(neg_inf(), neg_inf(), neg_inf(), neg_inf());
#pragma unroll
        for (int s = 0; s < SPLIT; ++s) {
            float4 v = __ldcg((const float4*)(p + (size_t)s * (N_ROWS * OUT_DIM)));
            m.x = fmaxf(m.x, v.x);
            m.y = fmaxf(m.y, v.y);
            m.z = fmaxf(m.z, v.z);
            m.w = fmaxf(m.w, v.w);
        }
        float4 b = *(const float4*)(bias + o4);
        m.x += b.x; m.y += b.y; m.z += b.z; m.w += b.w;
        *(float4*)(out + (size_t)n * OUT_DIM + o4) = m;
    }
}

extern "C" void kernel_launch(void* const* d_in, const int* in_sizes, int n_in,
                              void* d_out, int out_size)
{
    const float* x    = (const float*)d_in[0];   // [128, 1024]
    const float* w    = (const float*)d_in[1];   // [1024, 1024]
    const float* bias = (const float*)d_in[2];   // [1024]
    float* out = (float*)d_out;                  // [128, 1024]

    const int smem_bytes = (KS * 2 * TN + KS * TO) * sizeof(float);  // 64 KB
    static bool attr_set = false;
    if (!attr_set) {
        cudaFuncSetAttribute(tropical_fused_kernel,
                             cudaFuncAttributeMaxDynamicSharedMemorySize, smem_bytes);
        attr_set = true;
    }

    dim3 grid(OUT_DIM / TO, N_ROWS / TN, SPLIT);  // (8, 2, 16) = 256 CTAs
    tropical_fused_kernel<<<grid, 512, smem_bytes>>>(x, w, bias, out);
}